// round 6
// baseline (speedup 1.0000x reference)
#include <cuda_runtime.h>
#include <cuda_bf16.h>

// AttWModel — N=1024, L=2048, D=128
// out[n] = sum_l softmax_l( X[n,l]·q[n] ) * ( X[n,l]·v ),  q[n] = W^T z[n]
//
// R5b (resubmit after infra failure): persistent blocks + per-warp dynamic
// ticket queue over 32-row chunks. Absorbs HW finish-time spread that static
// splits cannot.

#define NB     1024
#define LSEQ   2048
#define DIM    128
#define NW     8
#define QGRP   8
#define CHROWS 32
#define CHPN   (LSEQ / CHROWS)      // 64 chunks per n
#define NCHUNK (NB * CHPN)          // 65536
#define PGRID  1184                  // 148 SMs * 8 blocks

__device__ float        g_q[NB * DIM];
__device__ float2       g_part[NCHUNK];
__device__ unsigned int g_ticket;    // zero-initialized; reset every launch

// ---------------------------------------------------------------------------
// Kernel 1: q = W^T z (W staged in smem, QGRP n per block) + ticket reset.
// ---------------------------------------------------------------------------
__global__ void __launch_bounds__(256) compute_q_kernel(
    const float* __restrict__ z, const float* __restrict__ W)
{
    __shared__ __align__(16) float Ws[DIM * DIM];
    __shared__ __align__(16) float zs[2 * DIM];

    const int tid = threadIdx.x;
    const int n0  = blockIdx.x * QGRP;

    if (blockIdx.x == 0 && tid == 0) g_ticket = 0u;   // reset for this launch

#pragma unroll
    for (int i = 0; i < (DIM * DIM) / (256 * 4); i++) {
        const int idx = (i * 256 + tid) * 4;
        reinterpret_cast<float4*>(Ws + idx)[0] =
            reinterpret_cast<const float4*>(W + idx)[0];
    }
    __syncthreads();

    const int d  = tid & (DIM - 1);
    const int ns = tid >> 7;

    for (int g = 0; g < QGRP; g += 2) {
        const int n = n0 + g + ns;
        if (tid < 2 * DIM) zs[tid] = z[(n0 + g) * DIM + tid];
        __syncthreads();

        const float* zrow = zs + ns * DIM;
        float a0 = 0.f, a1 = 0.f, a2 = 0.f, a3 = 0.f;
#pragma unroll
        for (int e = 0; e < DIM; e += 4) {
            a0 = fmaf(zrow[e + 0], Ws[(e + 0) * DIM + d], a0);
            a1 = fmaf(zrow[e + 1], Ws[(e + 1) * DIM + d], a1);
            a2 = fmaf(zrow[e + 2], Ws[(e + 2) * DIM + d], a2);
            a3 = fmaf(zrow[e + 3], Ws[(e + 3) * DIM + d], a3);
        }
        g_q[n * DIM + d] = (a0 + a1) + (a2 + a3);
        __syncthreads();
    }
}

// ---------------------------------------------------------------------------
// Kernel 2: persistent streaming. Warps independently pull 32-row chunks
// from a global ticket; per-chunk partial {Z,num} -> g_part[c].
// No intra-loop barriers -> cannot deadlock; warps exit when tickets drain.
// ---------------------------------------------------------------------------
__global__ void __launch_bounds__(NW * 32, 8) attw_persistent_kernel(
    const float* __restrict__ X,      // [NB, LSEQ, DIM]
    const float* __restrict__ v)      // [DIM]
{
    const int lane = threadIdx.x & 31;

    const float4 v4 = reinterpret_cast<const float4*>(v)[lane];

    for (;;) {
        unsigned int c = 0u;
        if (lane == 0) c = atomicAdd(&g_ticket, 1u);
        c = __shfl_sync(0xffffffffu, c, 0);
        if (c >= NCHUNK) break;

        const int n = (int)(c >> 6);                   // c / CHPN
        const float4 q4 = reinterpret_cast<const float4*>(g_q + n * DIM)[lane];

        const float4* Xp = reinterpret_cast<const float4*>(X)
                         + (size_t)c * (CHROWS * 32) + lane;

        float Z = 0.f, num = 0.f;
#pragma unroll 1
        for (int it = 0; it < CHROWS / 2; it++, Xp += 64) {
            const float4 x0 = __ldcs(Xp);
            const float4 x1 = __ldcs(Xp + 32);

            float s0 = x0.x*q4.x + x0.y*q4.y + x0.z*q4.z + x0.w*q4.w;
            float t0 = x0.x*v4.x + x0.y*v4.y + x0.z*v4.z + x0.w*v4.w;
            float s1 = x1.x*q4.x + x1.y*q4.y + x1.z*q4.z + x1.w*q4.w;
            float t1 = x1.x*v4.x + x1.y*v4.y + x1.z*v4.z + x1.w*v4.w;

#pragma unroll
            for (int off = 16; off > 0; off >>= 1) {
                s0 += __shfl_xor_sync(0xffffffffu, s0, off);
                s1 += __shfl_xor_sync(0xffffffffu, s1, off);
            }

            const float p0 = __expf(s0);
            const float p1 = __expf(s1);
            Z   += p0 + p1;
            num  = fmaf(p0, t0, fmaf(p1, t1, num));
        }

        // reduce per-lane value partials once per chunk
#pragma unroll
        for (int off = 16; off > 0; off >>= 1)
            num += __shfl_xor_sync(0xffffffffu, num, off);

        if (lane == 0) g_part[c] = make_float2(Z, num);
    }
}

// ---------------------------------------------------------------------------
// Kernel 3: finalize — warp per n. 64 float2 partials = 32 float4 loads.
// Fixed summation order -> deterministic output regardless of chunk->warp map.
// ---------------------------------------------------------------------------
__global__ void __launch_bounds__(256) finalize_kernel(float* __restrict__ out)
{
    const int lane = threadIdx.x & 31;
    const int n    = blockIdx.x * 8 + (threadIdx.x >> 5);

    const float4 d = reinterpret_cast<const float4*>(g_part)[n * 32 + lane];
    float Zt = d.x + d.z;
    float Nt = d.y + d.w;

#pragma unroll
    for (int off = 16; off > 0; off >>= 1) {
        Zt += __shfl_xor_sync(0xffffffffu, Zt, off);
        Nt += __shfl_xor_sync(0xffffffffu, Nt, off);
    }

    if (lane == 0) out[n] = Nt / Zt;

    // Belt-and-braces: also leave the ticket at 0 after the pipeline completes
    // (kernel 1 rewrites it anyway at the start of the next launch sequence).
    if (blockIdx.x == 0 && threadIdx.x == 0) g_ticket = 0u;
}

extern "C" void kernel_launch(void* const* d_in, const int* in_sizes, int n_in,
                              void* d_out, int out_size)
{
    const float* X = (const float*)d_in[0];
    const float* z = (const float*)d_in[1];
    const float* W = (const float*)d_in[2];
    const float* v = (const float*)d_in[3];
    float* out = (float*)d_out;

    compute_q_kernel<<<NB / QGRP, 256>>>(z, W);
    attw_persistent_kernel<<<PGRID, NW * 32>>>(X, v);
    finalize_kernel<<<NB / 8, 256>>>(out);
}

// round 7
// speedup vs baseline: 1.3030x; 1.3030x over previous
#include <cuda_runtime.h>
#include <cuda_bf16.h>

// AttWModel — N=1024, L=2048, D=128
// out[n] = sum_l softmax_l( X[n,l]·q[n] ) * ( X[n,l]·v ),  q[n] = W^T z[n]
//
// R7: R3 inner loop (best known), but grid = 1184 blocks = exact chip
// residency (148 SMs x 8 blocks). First NSPLIT n's are split into two
// 1024-row halves to create the extra 160 blocks. Static, deterministic.

#define NB     1024
#define LSEQ   2048
#define DIM    128
#define NW     8
#define QGRP   8
#define NSPLIT 160               // n's that are split in two halves
#define GRID2  (NB + NSPLIT)     // 1184 = 148 * 8

__device__ float  g_q[NB * DIM];
__device__ float2 g_part[NSPLIT * 2];   // {Z, num} per half, n < NSPLIT

// ---------------------------------------------------------------------------
// Kernel 1: q = W^T z, W staged in smem, QGRP n's per block.
// ---------------------------------------------------------------------------
__global__ void __launch_bounds__(256) compute_q_kernel(
    const float* __restrict__ z, const float* __restrict__ W)
{
    __shared__ __align__(16) float Ws[DIM * DIM];   // 64 KB
    __shared__ __align__(16) float zs[2 * DIM];

    const int tid = threadIdx.x;
    const int n0  = blockIdx.x * QGRP;

#pragma unroll
    for (int i = 0; i < (DIM * DIM) / (256 * 4); i++) {
        const int idx = (i * 256 + tid) * 4;
        reinterpret_cast<float4*>(Ws + idx)[0] =
            reinterpret_cast<const float4*>(W + idx)[0];
    }
    __syncthreads();

    const int d  = tid & (DIM - 1);
    const int ns = tid >> 7;

    for (int g = 0; g < QGRP; g += 2) {
        const int n = n0 + g + ns;
        if (tid < 2 * DIM) zs[tid] = z[(n0 + g) * DIM + tid];
        __syncthreads();

        const float* zrow = zs + ns * DIM;
        float a0 = 0.f, a1 = 0.f, a2 = 0.f, a3 = 0.f;
#pragma unroll
        for (int e = 0; e < DIM; e += 4) {
            a0 = fmaf(zrow[e + 0], Ws[(e + 0) * DIM + d], a0);
            a1 = fmaf(zrow[e + 1], Ws[(e + 1) * DIM + d], a1);
            a2 = fmaf(zrow[e + 2], Ws[(e + 2) * DIM + d], a2);
            a3 = fmaf(zrow[e + 3], Ws[(e + 3) * DIM + d], a3);
        }
        g_q[n * DIM + d] = (a0 + a1) + (a2 + a3);
        __syncthreads();
    }
}

// ---------------------------------------------------------------------------
// Kernel 2: streaming. 1184 blocks:
//   bid <  NSPLIT          : n = bid,          rows [0, 1024)    -> partial 0
//   NSPLIT <= bid < NB     : n = bid,          rows [0, 2048)    -> out[n]
//   bid >= NB              : n = bid - NB,     rows [1024, 2048) -> partial 1
// Inner loop identical to R3 (2-row unroll, score butterflies, deferred
// per-lane value accumulation, no max-shift, __expf, __ldcs).
// ---------------------------------------------------------------------------
__global__ void __launch_bounds__(NW * 32, 8) attw_stream_kernel(
    const float* __restrict__ X,      // [NB, LSEQ, DIM]
    const float* __restrict__ v,      // [DIM]
    float* __restrict__ out)          // [NB]
{
    const int bid  = blockIdx.x;
    const int lane = threadIdx.x & 31;
    const int wid  = threadIdx.x >> 5;

    int n, row0, rows;
    if (bid < NSPLIT)      { n = bid;      row0 = 0;        rows = LSEQ / 2; }
    else if (bid < NB)     { n = bid;      row0 = 0;        rows = LSEQ;     }
    else                   { n = bid - NB; row0 = LSEQ / 2; rows = LSEQ / 2; }

    const float4 q4 = reinterpret_cast<const float4*>(g_q + n * DIM)[lane];
    const float4 v4 = reinterpret_cast<const float4*>(v)[lane];

    const float4* Xp = reinterpret_cast<const float4*>(
        X + (size_t)n * LSEQ * DIM + (size_t)row0 * DIM)
        + (size_t)wid * 32 + lane;
    const float4* Xe = Xp + (size_t)(rows - wid) * 32;   // warp's end bound

    float Z = 0.f, num = 0.f;   // num: per-lane partial, reduced once at end

#pragma unroll 1
    for (; Xp < Xe; Xp += 2 * NW * 32) {
        const float4 x0 = __ldcs(Xp);
        const float4 x1 = __ldcs(Xp + NW * 32);

        float s0 = x0.x*q4.x + x0.y*q4.y + x0.z*q4.z + x0.w*q4.w;
        float t0 = x0.x*v4.x + x0.y*v4.y + x0.z*v4.z + x0.w*v4.w;
        float s1 = x1.x*q4.x + x1.y*q4.y + x1.z*q4.z + x1.w*q4.w;
        float t1 = x1.x*v4.x + x1.y*v4.y + x1.z*v4.z + x1.w*v4.w;

#pragma unroll
        for (int off = 16; off > 0; off >>= 1) {
            s0 += __shfl_xor_sync(0xffffffffu, s0, off);
            s1 += __shfl_xor_sync(0xffffffffu, s1, off);
        }

        const float p0 = __expf(s0);
        const float p1 = __expf(s1);
        Z   += p0 + p1;
        num  = fmaf(p0, t0, fmaf(p1, t1, num));
    }

#pragma unroll
    for (int off = 16; off > 0; off >>= 1)
        num += __shfl_xor_sync(0xffffffffu, num, off);

    __shared__ float sZ[NW], sN[NW];
    if (lane == 0) { sZ[wid] = Z; sN[wid] = num; }
    __syncthreads();

    if (threadIdx.x == 0) {
        float Zt = 0.f, Nt = 0.f;
#pragma unroll
        for (int w = 0; w < NW; w++) { Zt += sZ[w]; Nt += sN[w]; }
        if (bid >= NSPLIT && bid < NB) {
            out[n] = Nt / Zt;                       // whole-n block
        } else {
            const int half = (bid >= NB) ? 1 : 0;   // split-n partial
            g_part[n * 2 + half] = make_float2(Zt, Nt);
        }
    }
}

// ---------------------------------------------------------------------------
// Kernel 3: finalize the NSPLIT split n's.
// ---------------------------------------------------------------------------
__global__ void __launch_bounds__(NSPLIT) finalize_kernel(float* __restrict__ out)
{
    const int n = threadIdx.x;
    const float2 a = g_part[n * 2];
    const float2 b = g_part[n * 2 + 1];
    out[n] = (a.y + b.y) / (a.x + b.x);
}

extern "C" void kernel_launch(void* const* d_in, const int* in_sizes, int n_in,
                              void* d_out, int out_size)
{
    const float* X = (const float*)d_in[0];
    const float* z = (const float*)d_in[1];
    const float* W = (const float*)d_in[2];
    const float* v = (const float*)d_in[3];
    float* out = (float*)d_out;

    compute_q_kernel<<<NB / QGRP, 256>>>(z, W);
    attw_stream_kernel<<<GRID2, NW * 32>>>(X, v, out);
    finalize_kernel<<<1, NSPLIT>>>(out);
}

// round 8
// speedup vs baseline: 1.5026x; 1.1532x over previous
#include <cuda_runtime.h>
#include <cuda_bf16.h>

// AttWModel — N=1024, L=2048, D=128
// out[n] = sum_l softmax_l( X[n,l]·q[n] ) * ( X[n,l]·v ),  q[n] = W^T z[n]
//
// R8: flattened homogeneous partition. 1184 blocks (= 148 SMs x 8) each own
// rows [b*65536/37, (b+1)*65536/37) of the flattened 2^21-row space
// (1771/1772 rows, <=1 n-boundary). Two phases per block (n0, n0+1), all
// blocks write float4 partials; closed-form finalize. 9472 warps = 100% fill.

#define NB    1024
#define LSEQ  2048
#define DIM   128
#define NW    8
#define NBLK  1184

__device__ float  g_q[NB * DIM];
__device__ float4 g_part[NBLK];     // {Za, Na, Zb, Nb}

// ---------------------------------------------------------------------------
// Kernel 1: q = W^T z. 256 blocks x 512 threads, 4 n's per block, one (n,d)
// output per thread, W staged in smem.
// ---------------------------------------------------------------------------
__global__ void __launch_bounds__(512) compute_q_kernel(
    const float* __restrict__ z, const float* __restrict__ W)
{
    __shared__ __align__(16) float Ws[DIM * DIM];   // 64 KB
    __shared__ __align__(16) float zs[4 * DIM];

    const int tid = threadIdx.x;
    const int n0  = blockIdx.x * 4;

    // stage W (4096 float4 over 512 threads = 8 each, coalesced)
#pragma unroll
    for (int k = 0; k < 8; k++) {
        const int idx = k * 512 + tid;
        reinterpret_cast<float4*>(Ws)[idx] =
            reinterpret_cast<const float4*>(W)[idx];
    }
    // stage 4 z rows (512 floats)
    zs[tid] = z[n0 * DIM + tid];
    __syncthreads();

    const int d  = tid & (DIM - 1);
    const int nl = tid >> 7;                 // 0..3
    const float* zrow = zs + nl * DIM;

    float a0 = 0.f, a1 = 0.f, a2 = 0.f, a3 = 0.f;
#pragma unroll
    for (int e = 0; e < DIM; e += 4) {
        a0 = fmaf(zrow[e + 0], Ws[(e + 0) * DIM + d], a0);
        a1 = fmaf(zrow[e + 1], Ws[(e + 1) * DIM + d], a1);
        a2 = fmaf(zrow[e + 2], Ws[(e + 2) * DIM + d], a2);
        a3 = fmaf(zrow[e + 3], Ws[(e + 3) * DIM + d], a3);
    }
    g_q[(n0 + nl) * DIM + d] = (a0 + a1) + (a2 + a3);
}

// ---------------------------------------------------------------------------
// Phase worker: rows [r0, r1) of the flattened space, fixed n.
// Warp-strided (step NW), 2-row pairs, single-row tail.
// ---------------------------------------------------------------------------
__device__ __forceinline__ void phase_loop(
    const float4* __restrict__ Xf,   // X as float4, row r at Xf + r*32
    int r0, int r1, int wid, int lane,
    float4 q4, float4 v4, float& Z, float& num)
{
    int j = r0 + wid;
    const float4* p = Xf + (size_t)j * 32 + lane;

#pragma unroll 1
    for (; j + NW < r1; j += 2 * NW, p += 2 * NW * 32) {
        const float4 x0 = __ldcs(p);
        const float4 x1 = __ldcs(p + NW * 32);

        float s0 = x0.x*q4.x + x0.y*q4.y + x0.z*q4.z + x0.w*q4.w;
        float t0 = x0.x*v4.x + x0.y*v4.y + x0.z*v4.z + x0.w*v4.w;
        float s1 = x1.x*q4.x + x1.y*q4.y + x1.z*q4.z + x1.w*q4.w;
        float t1 = x1.x*v4.x + x1.y*v4.y + x1.z*v4.z + x1.w*v4.w;

#pragma unroll
        for (int off = 16; off > 0; off >>= 1) {
            s0 += __shfl_xor_sync(0xffffffffu, s0, off);
            s1 += __shfl_xor_sync(0xffffffffu, s1, off);
        }

        const float p0 = __expf(s0);
        const float p1 = __expf(s1);
        Z   += p0 + p1;
        num  = fmaf(p0, t0, fmaf(p1, t1, num));
    }
    if (j < r1) {                     // single-row tail
        const float4 x0 = __ldcs(p);
        float s0 = x0.x*q4.x + x0.y*q4.y + x0.z*q4.z + x0.w*q4.w;
        float t0 = x0.x*v4.x + x0.y*v4.y + x0.z*v4.z + x0.w*v4.w;
#pragma unroll
        for (int off = 16; off > 0; off >>= 1)
            s0 += __shfl_xor_sync(0xffffffffu, s0, off);
        const float p0 = __expf(s0);
        Z   += p0;
        num  = fmaf(p0, t0, num);
    }
}

// ---------------------------------------------------------------------------
// Kernel 2: streaming. Block b: rows [b*65536/37, (b+1)*65536/37).
// Phase A = rows of n0, phase B = rows of n0+1 (may be empty).
// ---------------------------------------------------------------------------
__global__ void __launch_bounds__(NW * 32, 8) attw_stream_kernel(
    const float* __restrict__ X,      // [NB*LSEQ, DIM] flattened
    const float* __restrict__ v)      // [DIM]
{
    const int bid  = blockIdx.x;
    const int lane = threadIdx.x & 31;
    const int wid  = threadIdx.x >> 5;

    const unsigned R0 = ((unsigned)bid << 16) / 37u;
    const unsigned R1 = (((unsigned)bid + 1u) << 16) / 37u;
    const int n0   = (int)(R0 >> 11);
    const int bRow = (int)min(R1, (unsigned)(n0 + 1) << 11);

    const float4* Xf = reinterpret_cast<const float4*>(X);
    const float4  v4 = reinterpret_cast<const float4*>(v)[lane];

    __shared__ float sZa[NW], sNa[NW], sZb[NW], sNb[NW];

    // Phase A: n0
    {
        const float4 q4 = reinterpret_cast<const float4*>(g_q + n0 * DIM)[lane];
        float Z = 0.f, num = 0.f;
        phase_loop(Xf, (int)R0, bRow, wid, lane, q4, v4, Z, num);
#pragma unroll
        for (int off = 16; off > 0; off >>= 1)
            num += __shfl_xor_sync(0xffffffffu, num, off);
        if (lane == 0) { sZa[wid] = Z; sNa[wid] = num; }
    }

    // Phase B: n0 + 1 (empty if bRow == R1)
    {
        float Z = 0.f, num = 0.f;
        if (bRow < (int)R1) {
            const float4 q4 =
                reinterpret_cast<const float4*>(g_q + (n0 + 1) * DIM)[lane];
            phase_loop(Xf, bRow, (int)R1, wid, lane, q4, v4, Z, num);
#pragma unroll
            for (int off = 16; off > 0; off >>= 1)
                num += __shfl_xor_sync(0xffffffffu, num, off);
        }
        if (lane == 0) { sZb[wid] = Z; sNb[wid] = num; }
    }

    __syncthreads();

    if (threadIdx.x == 0) {
        float Za = 0.f, Na = 0.f, Zb = 0.f, Nb = 0.f;
#pragma unroll
        for (int w = 0; w < NW; w++) {
            Za += sZa[w]; Na += sNa[w];
            Zb += sZb[w]; Nb += sNb[w];
        }
        g_part[bid] = make_float4(Za, Na, Zb, Nb);
    }
}

// ---------------------------------------------------------------------------
// Kernel 3: finalize. Thread n sums partials of the <=3 blocks overlapping n.
// Block containing row r: b(r) = (37r + 36) >> 16.
// ---------------------------------------------------------------------------
__global__ void __launch_bounds__(256) finalize_kernel(float* __restrict__ out)
{
    const int n = blockIdx.x * 256 + threadIdx.x;
    if (n >= NB) return;

    const unsigned rlo = (unsigned)n << 11;
    const unsigned rhi = ((unsigned)(n + 1) << 11) - 1u;
    const unsigned bs  = (37u * rlo + 36u) >> 16;
    const unsigned be  = (37u * rhi + 36u) >> 16;

    float Zt = 0.f, Nt = 0.f;
    for (unsigned b = bs; b <= be; b++) {
        const int n0b = (int)(((b << 16) / 37u) >> 11);
        const float4 pw = g_part[b];
        if (n0b == n)          { Zt += pw.x; Nt += pw.y; }
        else if (n0b + 1 == n) { Zt += pw.z; Nt += pw.w; }
    }
    out[n] = Nt / Zt;
}

extern "C" void kernel_launch(void* const* d_in, const int* in_sizes, int n_in,
                              void* d_out, int out_size)
{
    const float* X = (const float*)d_in[0];
    const float* z = (const float*)d_in[1];
    const float* W = (const float*)d_in[2];
    const float* v = (const float*)d_in[3];
    float* out = (float*)d_out;

    compute_q_kernel<<<NB / 4, 512>>>(z, W);
    attw_stream_kernel<<<NBLK, NW * 32>>>(X, v);
    finalize_kernel<<<(NB + 255) / 256, 256>>>(out);
}